// round 9
// baseline (speedup 1.0000x reference)
#include <cuda_runtime.h>
#include <cuda_fp16.h>
#include <stdint.h>

// RayCastLayer as a split-fp16 GEMM (classic mma.sync path).
//   out[2048 x 361] = x[2048 x 361] * M[361 x 361]
// M = symmetric ray operator built from `weight`.
// Split: out = xhi*Mhi + xlo*Mhi + xhi*Mlo (lo*lo dropped, ~2^-22).
// R9: vectorized prep_x + low-register gemm (A and B both via cp.async +
// ldmatrix, fragment addressing identical to the R7-verified kernel).

#define BOARD 19
#define NPOS  361
#define KP    384               // padded K
#define LDK   768               // g_A/g_B row pitch in halves: [hi 384 | lo 384]
#define MT    32                // CTA tile M
#define NT    64                // CTA tile N
#define KC    32                // k per pipeline chunk
#define NCHK  12                // 384 / 32
#define SPITCH 72               // smem row pitch in halves (144B)

#define A_STAGE_B (MT * SPITCH * 2)            // 4608 bytes
#define B_STAGE_B (NT * SPITCH * 2)            // 9216 bytes
#define STAGE_B   (A_STAGE_B + B_STAGE_B)      // 13824 bytes

__device__ __align__(16) __half g_A[2048 * LDK];  // [m][ xhi(384) | xlo(384) ]
__device__ __align__(16) __half g_B[KP * LDK];    // [n][ Mhi(384) | Mlo(384) ]

// ---------------- prep kernels ----------------------------------------------

// One thread handles 8 consecutive k of one row: 8 LDG.32 -> 2x STG.128.
__global__ void prep_x(const float* __restrict__ x, int nplanes) {
    int id = blockIdx.x * blockDim.x + threadIdx.x;
    if (id >= nplanes * (KP / 8)) return;
    int m  = id / (KP / 8);
    int q0 = (id - m * (KP / 8)) * 8;
    uint32_t hw[4], lw[4];
    #pragma unroll
    for (int i = 0; i < 4; i++) {
        int q = q0 + 2 * i;
        float v0 = (q     < NPOS) ? x[m * NPOS + q]     : 0.f;
        float v1 = (q + 1 < NPOS) ? x[m * NPOS + q + 1] : 0.f;
        __half2 h = __floats2half2_rn(v0, v1);
        float2 hf = __half22float2(h);
        __half2 l = __floats2half2_rn(v0 - hf.x, v1 - hf.y);
        hw[i] = *reinterpret_cast<uint32_t*>(&h);
        lw[i] = *reinterpret_cast<uint32_t*>(&l);
    }
    uint4* dst_h = reinterpret_cast<uint4*>(g_A + m * LDK + q0);
    uint4* dst_l = reinterpret_cast<uint4*>(g_A + m * LDK + KP + q0);
    *dst_h = make_uint4(hw[0], hw[1], hw[2], hw[3]);
    *dst_l = make_uint4(lw[0], lw[1], lw[2], lw[3]);
}

__global__ void prep_B(const float* __restrict__ w) {
    int id = blockIdx.x * blockDim.x + threadIdx.x;
    if (id >= KP * (KP / 2)) return;
    int n  = id / (KP / 2);
    int qi = id - n * (KP / 2);
    uint32_t hw = 0, lw = 0;
    #pragma unroll
    for (int j = 0; j < 2; j++) {
        int q = qi * 2 + j;
        float val = 0.f;
        if (n < NPOS && q < NPOS) {
            int yn = n / BOARD, xn = n - yn * BOARD;
            int yq = q / BOARD, xq = q - yq * BOARD;
            int dy = yq - yn, dx = xq - xn;
            int ady = dy < 0 ? -dy : dy, adx = dx < 0 ? -dx : dx;
            if (!(dy == 0 && dx == 0)) {
                if      (dx == 0)    val = w[ady - 1];
                else if (dy == 0)    val = w[adx - 1];
                else if (ady == adx) val = w[18 + ady - 1];
            }
        }
        __half h = __float2half_rn(val);
        __half l = __float2half_rn(val - __half2float(h));
        hw |= (uint32_t)__half_as_ushort(h) << (16 * j);
        lw |= (uint32_t)__half_as_ushort(l) << (16 * j);
    }
    uint32_t* B32 = reinterpret_cast<uint32_t*>(g_B);
    B32[n * (LDK / 2) + qi]          = hw;
    B32[n * (LDK / 2) + KP / 2 + qi] = lw;
}

// ---------------- GEMM helpers ----------------------------------------------

__device__ __forceinline__ void ldmx4(uint32_t* r, uint32_t addr) {
    asm volatile("ldmatrix.sync.aligned.m8n8.x4.shared.b16 {%0,%1,%2,%3}, [%4];"
                 : "=r"(r[0]), "=r"(r[1]), "=r"(r[2]), "=r"(r[3]) : "r"(addr));
}

__device__ __forceinline__ void mma16816(float* d, const uint32_t* a, const uint32_t* b) {
    asm volatile("mma.sync.aligned.m16n8k16.row.col.f32.f16.f16.f32 "
                 "{%0,%1,%2,%3}, {%4,%5,%6,%7}, {%8,%9}, {%0,%1,%2,%3};"
                 : "+f"(d[0]), "+f"(d[1]), "+f"(d[2]), "+f"(d[3])
                 : "r"(a[0]), "r"(a[1]), "r"(a[2]), "r"(a[3]), "r"(b[0]), "r"(b[1]));
}

// Load one chunk: A rows [m0,m0+32) + B rows [n0,n0+64), k cols [kb,kb+32)
// of both hi and lo segments. (256 + 512) granules of 16B, 128 threads x 6.
__device__ __forceinline__ void load_chunk(uint32_t sa, uint32_t sbB,
                                           int m0, int n0, int kb, int tid) {
    #pragma unroll
    for (int i = 0; i < 6; i++) {
        int id = tid + i * 128;           // 0..767
        int isB = (id >= 256);
        int l   = isB ? (id - 256) : id;
        int r   = l >> 3;                 // A: 0..31   B: 0..63
        int gq  = l & 7;
        int seg = gq >> 2;                // 0 = hi, 1 = lo
        int t   = gq & 3;
        const __half* src = (isB ? g_B + (n0 + r) * LDK : g_A + (m0 + r) * LDK)
                            + seg * KP + kb + t * 8;
        uint32_t dst = (isB ? sbB : sa)
                     + (uint32_t)(r * (SPITCH * 2) + seg * 64 + t * 16);
        asm volatile("cp.async.ca.shared.global [%0], [%1], 16;" :: "r"(dst), "l"(src));
    }
    asm volatile("cp.async.commit_group;" ::: "memory");
}

__global__ __launch_bounds__(128, 6)
void gemm_kernel(float* __restrict__ out, int nplanes)
{
    __shared__ __align__(16) __half stg[2 * STAGE_B / 2];

    const int tid  = threadIdx.x;
    const int lane = tid & 31;
    const int wid  = tid >> 5;
    const int wm   = wid & 1;             // warp grid 2(m) x 2(n); warp tile 16 x 32
    const int wn   = wid >> 1;
    const int m0   = blockIdx.x * MT;
    const int n0   = blockIdx.y * NT;

    uint32_t sbase = (uint32_t)__cvta_generic_to_shared(&stg[0]);
    const uint32_t sa[2] = { sbase,             sbase + STAGE_B };
    const uint32_t sb[2] = { sbase + A_STAGE_B, sbase + STAGE_B + A_STAGE_B };

    // ldmatrix lane addressing (R7-verified):
    const int mat = lane >> 3;
    const int mr  = lane & 7;
    // A: row = wm*16 + (mat&1)*8 + mr ; k += (mat>>1)*8
    const uint32_t aRow = (uint32_t)((wm * 16 + (mat & 1) * 8 + mr) * (SPITCH * 2));
    const uint32_t aKof = (uint32_t)((mat >> 1) * 16);
    // B: row = wn*32 + p*16 + (mat>>1)*8 + mr ; k += (mat&1)*8
    const uint32_t bRow = (uint32_t)((wn * 32 + (mat >> 1) * 8 + mr) * (SPITCH * 2));
    const uint32_t bKof = (uint32_t)((mat & 1) * 16);

    float acc[4][4];
    #pragma unroll
    for (int i = 0; i < 4; i++)
        #pragma unroll
        for (int j = 0; j < 4; j++) acc[i][j] = 0.f;

    load_chunk(sa[0], sb[0], m0, n0, 0, tid);

    #pragma unroll 1
    for (int c = 0; c < NCHK; c++) {
        if (c + 1 < NCHK) {
            load_chunk(sa[(c + 1) & 1], sb[(c + 1) & 1], m0, n0, (c + 1) * KC, tid);
            asm volatile("cp.async.wait_group 1;" ::: "memory");
        } else {
            asm volatile("cp.async.wait_group 0;" ::: "memory");
        }
        __syncthreads();

        const uint32_t au = sa[c & 1];
        const uint32_t bu = sb[c & 1];

        #pragma unroll
        for (int s = 0; s < 2; s++) {                 // two k16 steps per chunk
            uint32_t ah[4], al[4];
            {
                uint32_t base = au + aRow + (uint32_t)(s * 32) + aKof;
                ldmx4(ah, base);          // hi
                ldmx4(al, base + 64);     // lo (+32 halves)
            }
            uint32_t bh[4][2], bl[4][2];
            #pragma unroll
            for (int p = 0; p < 2; p++) {
                uint32_t base = bu + bRow + (uint32_t)(p * 16 * (SPITCH * 2))
                              + (uint32_t)(s * 32) + bKof;
                uint32_t rh[4], rl[4];
                ldmx4(rh, base);
                ldmx4(rl, base + 64);
                bh[p*2+0][0] = rh[0]; bh[p*2+0][1] = rh[1];
                bh[p*2+1][0] = rh[2]; bh[p*2+1][1] = rh[3];
                bl[p*2+0][0] = rl[0]; bl[p*2+0][1] = rl[1];
                bl[p*2+1][0] = rl[2]; bl[p*2+1][1] = rl[3];
            }
            // term-major: same-acc reuse distance = 4
            #pragma unroll
            for (int nf = 0; nf < 4; nf++) mma16816(acc[nf], ah, bh[nf]); // hi*hi
            #pragma unroll
            for (int nf = 0; nf < 4; nf++) mma16816(acc[nf], al, bh[nf]); // lo*hi
            #pragma unroll
            for (int nf = 0; nf < 4; nf++) mma16816(acc[nf], ah, bl[nf]); // hi*lo
        }
        __syncthreads();
    }

    // ---- epilogue: direct stores ----
    const int g  = lane >> 2;
    const int tg = lane & 3;
    const int m  = m0 + wm * 16 + g;
    #pragma unroll
    for (int nf = 0; nf < 4; nf++) {
        const int n = n0 + wn * 32 + nf * 8 + 2 * tg;
        if (m < nplanes) {
            if (n     < NPOS) out[m * NPOS + n]     = acc[nf][0];
            if (n + 1 < NPOS) out[m * NPOS + n + 1] = acc[nf][1];
        }
        if (m + 8 < nplanes) {
            if (n     < NPOS) out[(m + 8) * NPOS + n]     = acc[nf][2];
            if (n + 1 < NPOS) out[(m + 8) * NPOS + n + 1] = acc[nf][3];
        }
    }
}

// ---------------- launch -----------------------------------------------------

extern "C" void kernel_launch(void* const* d_in, const int* in_sizes, int n_in,
                              void* d_out, int out_size)
{
    const float* x      = (const float*)d_in[0];   // [32,64,19,19]
    const float* weight = (const float*)d_in[1];   // [2,18]
    float* out          = (float*)d_out;

    const int nplanes = in_sizes[0] / NPOS;        // 2048

    prep_x<<<(nplanes * (KP / 8) + 255) / 256, 256>>>(x, nplanes);
    prep_B<<<(KP * (KP / 2) + 255) / 256, 256>>>(weight);

    dim3 grid((nplanes + MT - 1) / MT, (NPOS + NT - 1) / NT);   // 64 x 6
    gemm_kernel<<<grid, 128>>>(out, nplanes);
}

// round 10
// speedup vs baseline: 1.5044x; 1.5044x over previous
#include <cuda_runtime.h>
#include <cuda_bf16.h>
#include <stdint.h>

// RayCastLayer via Toeplitz line-transform factorization (R10: scheduling round).
// Identical algorithm/thread-mapping to the verified R5 kernel; the hot-loop
// shared loads are now plain C++ (NOT volatile asm) so ptxas can hoist and
// software-pipeline the 19 independent LDS.128s per pass. FFMA2 asm is pure.

#define BOARD 19
#define NPOS  361
#define PW    55            // padded tile width (x shifted by +18)
#define TILE  (BOARD * PW)  // 1045 ulonglong2 entries (4 planes as 2x f32x2)
#define PLANES 4
#define THREADS 256

typedef unsigned long long u64;

#define FMA2(a, x, y) asm("fma.rn.f32x2 %0, %1, %2, %0;" : "+l"(a) : "l"(x), "l"(y))
#define ADD2(a, x)    asm("add.rn.f32x2 %0, %0, %1;"     : "+l"(a) : "l"(x))

// One line-transform pass: 19 k-steps, 4 outputs x 4 planes.
// t: tile base for this thread's line (element stride STRIDE).
// w: weight row base = wrow(y0) with per-k stride of 20 u64 (16B-aligned pairs).
template <int STRIDE>
__device__ __forceinline__ void pass4(const ulonglong2* __restrict__ t,
                                      const u64* __restrict__ w,
                                      u64 acc[8])
{
    #pragma unroll
    for (int k = 0; k < BOARD; k++) {
        const ulonglong2 v   = t[k * STRIDE];
        const ulonglong2 w01 = *reinterpret_cast<const ulonglong2*>(w + k * 20);
        const ulonglong2 w23 = *reinterpret_cast<const ulonglong2*>(w + k * 20 + 2);
        FMA2(acc[0], v.x, w01.x);  FMA2(acc[1], v.y, w01.x);
        FMA2(acc[2], v.x, w01.y);  FMA2(acc[3], v.y, w01.y);
        FMA2(acc[4], v.x, w23.x);  FMA2(acc[5], v.y, w23.x);
        FMA2(acc[6], v.x, w23.y);  FMA2(acc[7], v.y, w23.y);
    }
}

__device__ __forceinline__ u64 dupf(float w) {
    u64 u;
    const uint32_t b = __float_as_uint(w);
    asm("mov.b64 %0, {%1,%1};" : "=l"(u) : "r"(b));
    return u;
}

__global__ __launch_bounds__(THREADS, 3)
void raycast_kernel(const float* __restrict__ x,
                    const float* __restrict__ weight,
                    float* __restrict__ out,
                    int nplanes)
{
    __shared__ ulonglong2 t0[TILE];                   // padded [19][55] x 4 planes
    __shared__ ulonglong2 bufV[NPOS];                 // per-family partials
    __shared__ ulonglong2 bufH[NPOS];
    __shared__ ulonglong2 bufD1[NPOS];
    __shared__ ulonglong2 bufD2[NPOS];
    __shared__ __align__(16) u64 wlp[BOARD * 20];     // WL^T dup pairs [k][y]
    __shared__ __align__(16) u64 wdp[BOARD * 20];     // WD^T dup pairs

    const int tid = threadIdx.x;
    const int g0  = blockIdx.x * PLANES;

    // ---- zero ONLY the lateral pad columns ----
    #pragma unroll
    for (int i = tid; i < BOARD * 36; i += THREADS) {
        const int y = i / 36;
        const int c = i - y * 36;
        const int col = (c < 18) ? c : (c + BOARD);   // cols [0,18) and [37,55)
        t0[y * PW + col] = make_ulonglong2(0ull, 0ull);
    }

    // ---- packed duplicated Toeplitz weights: [k][y], y padded to 20 ----
    #pragma unroll
    for (int i = tid; i < BOARD * 20; i += THREADS) {
        const int k = i / 20;
        const int y = i - k * 20;
        const int d = (k > y) ? (k - y) : (y - k);
        const bool v = (y < BOARD) && (d > 0);
        wlp[i] = dupf(v ? weight[d - 1]      : 0.0f);
        wdp[i] = dupf(v ? weight[18 + d - 1] : 0.0f);
    }

    // ---- data fill: per position, 4 planes -> one STS.128 ----
    const bool full = (g0 + PLANES <= nplanes);
    float4* t0f4 = reinterpret_cast<float4*>(t0);
    #pragma unroll
    for (int p = tid; p < NPOS; p += THREADS) {
        const int yy = p / BOARD;
        const int xx = p - yy * BOARD;
        float4 v;
        if (full) {
            v.x = x[(g0 + 0) * NPOS + p];
            v.y = x[(g0 + 1) * NPOS + p];
            v.z = x[(g0 + 2) * NPOS + p];
            v.w = x[(g0 + 3) * NPOS + p];
        } else {
            v.x = (g0 + 0 < nplanes) ? x[(g0 + 0) * NPOS + p] : 0.f;
            v.y = (g0 + 1 < nplanes) ? x[(g0 + 1) * NPOS + p] : 0.f;
            v.z = (g0 + 2 < nplanes) ? x[(g0 + 2) * NPOS + p] : 0.f;
            v.w = (g0 + 3 < nplanes) ? x[(g0 + 3) * NPOS + p] : 0.f;
        }
        t0f4[yy * PW + xx + 18] = v;
    }
    __syncthreads();

    u64 acc[8];

    if (tid < 128) {
        // ---- pass V: outputs (y0+r, xx), reads s[k][xx], stride PW ----
        if (tid < 95) {
            #pragma unroll
            for (int i = 0; i < 8; i++) acc[i] = 0ull;
            const int yg = tid / BOARD;
            const int xx = tid - yg * BOARD;
            const int y0 = 4 * yg;
            pass4<PW>(t0 + (xx + 18), wlp + y0, acc);
            #pragma unroll
            for (int r = 0; r < 4; r++) {
                const int yy = y0 + r;
                if (yy < BOARD)
                    bufV[yy * BOARD + xx] = make_ulonglong2(acc[r*2+0], acc[r*2+1]);
            }
        }
        // ---- pass D1: outputs (y0+r, xb+r), stride PW+1 ----
        if (tid < 110) {
            #pragma unroll
            for (int i = 0; i < 8; i++) acc[i] = 0ull;
            const int yg = tid / 22;
            const int xb = (tid - yg * 22) - 3;
            const int y0 = 4 * yg;
            int b = xb - y0 + 18;
            if (b < 0) b = 0;                // only the fully-invalid corner thread
            pass4<PW + 1>(t0 + b, wdp + y0, acc);
            #pragma unroll
            for (int r = 0; r < 4; r++) {
                const int yy = y0 + r;
                const int xx = xb + r;
                if ((yy < BOARD) && (xx >= 0) && (xx < BOARD))
                    bufD1[yy * BOARD + xx] = make_ulonglong2(acc[r*2+0], acc[r*2+1]);
            }
        }
    } else {
        const int gt = tid - 128;
        // ---- pass H: outputs (yy, x0+r), reads s[yy][k], stride 1 ----
        if (gt < 95) {
            #pragma unroll
            for (int i = 0; i < 8; i++) acc[i] = 0ull;
            const int yy = gt / 5;
            const int xg = gt - yy * 5;
            const int x0 = 4 * xg;
            pass4<1>(t0 + (yy * PW + 18), wlp + x0, acc);
            #pragma unroll
            for (int r = 0; r < 4; r++) {
                const int xx = x0 + r;
                if (xx < BOARD)
                    bufH[yy * BOARD + xx] = make_ulonglong2(acc[r*2+0], acc[r*2+1]);
            }
        }
        // ---- pass D2: outputs (y0+r, xb-r), stride PW-1 ----
        if (gt < 110) {
            #pragma unroll
            for (int i = 0; i < 8; i++) acc[i] = 0ull;
            const int yg = gt / 22;
            const int xb = gt - yg * 22;     // 0..21
            const int y0 = 4 * yg;
            const int b  = xb + y0 + 18;     // worst overflow reads zero pad
            pass4<PW - 1>(t0 + b, wdp + y0, acc);
            #pragma unroll
            for (int r = 0; r < 4; r++) {
                const int yy = y0 + r;
                const int xx = xb - r;
                if ((yy < BOARD) && (xx >= 0) && (xx < BOARD))
                    bufD2[yy * BOARD + xx] = make_ulonglong2(acc[r*2+0], acc[r*2+1]);
            }
        }
    }

    __syncthreads();

    // ---- combine 4 partials and store (coalesced per plane) ----
    #pragma unroll
    for (int p = tid; p < NPOS; p += THREADS) {
        const ulonglong2 A = bufV[p];
        const ulonglong2 B = bufH[p];
        const ulonglong2 C = bufD1[p];
        const ulonglong2 D = bufD2[p];
        u64 s0 = A.x, s1 = A.y;
        ADD2(s0, B.x);  ADD2(s0, C.x);  ADD2(s0, D.x);
        ADD2(s1, B.y);  ADD2(s1, C.y);  ADD2(s1, D.y);
        uint32_t p0, p1, p2, p3;
        asm("mov.b64 {%0,%1}, %2;" : "=r"(p0), "=r"(p1) : "l"(s0));
        asm("mov.b64 {%0,%1}, %2;" : "=r"(p2), "=r"(p3) : "l"(s1));
        if (full) {
            out[(g0 + 0) * NPOS + p] = __uint_as_float(p0);
            out[(g0 + 1) * NPOS + p] = __uint_as_float(p1);
            out[(g0 + 2) * NPOS + p] = __uint_as_float(p2);
            out[(g0 + 3) * NPOS + p] = __uint_as_float(p3);
        } else {
            if (g0 + 0 < nplanes) out[(g0 + 0) * NPOS + p] = __uint_as_float(p0);
            if (g0 + 1 < nplanes) out[(g0 + 1) * NPOS + p] = __uint_as_float(p1);
            if (g0 + 2 < nplanes) out[(g0 + 2) * NPOS + p] = __uint_as_float(p2);
            if (g0 + 3 < nplanes) out[(g0 + 3) * NPOS + p] = __uint_as_float(p3);
        }
    }
}

extern "C" void kernel_launch(void* const* d_in, const int* in_sizes, int n_in,
                              void* d_out, int out_size)
{
    const float* x      = (const float*)d_in[0];   // [32,64,19,19]
    const float* weight = (const float*)d_in[1];   // [2,18]
    float* out          = (float*)d_out;

    const int nplanes = in_sizes[0] / NPOS;        // 2048
    const int grid = (nplanes + PLANES - 1) / PLANES;   // 512

    raycast_kernel<<<grid, THREADS>>>(x, weight, out, nplanes);
}

// round 11
// speedup vs baseline: 1.7694x; 1.1762x over previous
#include <cuda_runtime.h>
#include <cuda_bf16.h>
#include <stdint.h>

// RayCastLayer, R11: full-line threads + register-resident Toeplitz weights.
// Each thread computes ALL 19 outputs of one line (column / row / diagonal /
// anti-diagonal) for 2 planes packed as f32x2. Because the output index range
// is fixed [0,19), the weight index |k-j| is compile-time -> the 18 duplicated
// weight pairs live in registers; the fully unrolled 19x19 loop does
// 1 LDS.64 + 18 FFMA2 per k. All four families execute identical code with
// runtime (base, stride, weight set) -> full warps, no divergence.
// CTA = 224 threads = 2 groups x (19 V + 19 H + 37 D1 + 37 D2) lines,
// 4 planes per CTA. Diagonals padded to length 19 via lateral zero-pad.

#define BOARD 19
#define NPOS  361
#define PW    55            // padded tile width (x shifted by +18)
#define TILE  (BOARD * PW)  // 1045 u64 entries per 2-plane group
#define THREADS 224
#define PLANES 4            // 2 groups x 2 planes

typedef unsigned long long u64;

#define FMA2(a, x, y) asm("fma.rn.f32x2 %0, %1, %2, %0;" : "+l"(a) : "l"(x), "l"(y))
#define ADD2(a, x)    asm("add.rn.f32x2 %0, %0, %1;"     : "+l"(a) : "l"(x))

__device__ __forceinline__ u64 dupf(float w) {
    u64 u;
    const uint32_t b = __float_as_uint(w);
    asm("mov.b64 %0, {%1,%1};" : "=l"(u) : "r"(b));
    return u;
}

__global__ __launch_bounds__(THREADS, 3)
void raycast_kernel(const float* __restrict__ x,
                    const float* __restrict__ weight,
                    float* __restrict__ out,
                    int nplanes)
{
    __shared__ u64 tile[2][TILE];          // [group][19][55], 2 planes as f32x2
    __shared__ u64 bufV[2][NPOS];          // per-family partials per group
    __shared__ u64 bufH[2][NPOS];
    __shared__ u64 bufD1[2][NPOS];
    __shared__ u64 bufD2[2][NPOS];
    __shared__ u64 wls[18], wds[18];       // duplicated weight pairs

    const int tid = threadIdx.x;
    const int g0  = blockIdx.x * PLANES;

    // ---- weights (line / diagonal), duplicated pairs ----
    if (tid < 36) {
        const int f = tid / 18, d = tid - f * 18;
        const u64 v = dupf(weight[f * 18 + d]);
        if (f == 0) wls[d] = v; else wds[d] = v;
    }

    // ---- zero lateral pad columns (disjoint from data fill) ----
    for (int i = tid; i < 2 * BOARD * 36; i += THREADS) {
        const int gg = i / (BOARD * 36);
        const int r  = i - gg * (BOARD * 36);
        const int y  = r / 36;
        const int c  = r - y * 36;
        const int col = (c < 18) ? c : (c + BOARD);   // [0,18) and [37,55)
        tile[gg][y * PW + col] = 0ull;
    }

    // ---- data fill: pack 2 planes per group into f32x2 ----
    for (int i = tid; i < 2 * NPOS; i += THREADS) {
        const int gg = i / NPOS;
        const int p  = i - gg * NPOS;
        const int yy = p / BOARD;
        const int xx = p - yy * BOARD;
        const int pl = g0 + gg * 2;
        const float v0 = (pl     < nplanes) ? x[pl * NPOS + p]       : 0.f;
        const float v1 = (pl + 1 < nplanes) ? x[(pl + 1) * NPOS + p] : 0.f;
        u64 v;
        asm("mov.b64 %0, {%1,%2};" : "=l"(v)
            : "r"(__float_as_uint(v0)), "r"(__float_as_uint(v1)));
        tile[gg][yy * PW + xx + 18] = v;
    }
    __syncthreads();

    // ---- per-thread line parameters (uniform code across families) ----
    const int grp = tid / 112;
    const int lt  = tid - grp * 112;

    int base, stride, fam, line;
    if (lt < 19)      { fam = 0; line = lt;      base = line + 18;      stride = PW;     }
    else if (lt < 38) { fam = 1; line = lt - 19; base = line * PW + 18; stride = 1;      }
    else if (lt < 75) { fam = 2; line = lt - 38; base = line;           stride = PW + 1; }
    else              { fam = 3; line = lt - 75; base = line + 18;      stride = PW - 1; }
    // fam2 (D1): cell k at (y=k, x=line-18+k) -> idx = k*PW + (line+k)
    // fam3 (D2): cell k at (y=k, x=line-k)    -> idx = k*PW + (line-k+18)

    // ---- weight pairs into registers (compile-time indexed below) ----
    const u64* wsel = (fam < 2) ? wls : wds;
    u64 wr[18];
    #pragma unroll
    for (int i = 0; i < 18; i++) wr[i] = wsel[i];

    const u64* tp = tile[grp];
    u64 acc[19];
    #pragma unroll
    for (int j = 0; j < 19; j++) acc[j] = 0ull;

    // ---- the transform: 19 loads, 342 FFMA2, weights from registers ----
    #pragma unroll
    for (int k = 0; k < BOARD; k++) {
        const u64 v = tp[base + k * stride];
        #pragma unroll
        for (int j = 0; j < BOARD; j++) {
            if (j == k) continue;
            const int d = (k > j) ? (k - j) : (j - k);
            FMA2(acc[j], v, wr[d - 1]);
        }
    }

    // ---- scatter line outputs to this family's partial buffer ----
    if (fam == 0) {
        #pragma unroll
        for (int j = 0; j < BOARD; j++) bufV[grp][j * BOARD + line] = acc[j];
    } else if (fam == 1) {
        #pragma unroll
        for (int j = 0; j < BOARD; j++) bufH[grp][line * BOARD + j] = acc[j];
    } else if (fam == 2) {
        const int off = line - 18;            // x = j + off
        #pragma unroll
        for (int j = 0; j < BOARD; j++) {
            const int xx = j + off;
            if (xx >= 0 && xx < BOARD) bufD1[grp][j * BOARD + xx] = acc[j];
        }
    } else {
        #pragma unroll
        for (int j = 0; j < BOARD; j++) {     // x = line - j
            const int xx = line - j;
            if (xx >= 0 && xx < BOARD) bufD2[grp][j * BOARD + xx] = acc[j];
        }
    }

    __syncthreads();

    // ---- combine 4 partials, unpack, coalesced store per plane ----
    for (int i = tid; i < 2 * NPOS; i += THREADS) {
        const int gg = i / NPOS;
        const int p  = i - gg * NPOS;
        u64 s = bufV[gg][p];
        ADD2(s, bufH[gg][p]);
        ADD2(s, bufD1[gg][p]);
        ADD2(s, bufD2[gg][p]);
        uint32_t p0, p1;
        asm("mov.b64 {%0,%1}, %2;" : "=r"(p0), "=r"(p1) : "l"(s));
        const int pl = g0 + gg * 2;
        if (pl     < nplanes) out[pl * NPOS + p]       = __uint_as_float(p0);
        if (pl + 1 < nplanes) out[(pl + 1) * NPOS + p] = __uint_as_float(p1);
    }
}

extern "C" void kernel_launch(void* const* d_in, const int* in_sizes, int n_in,
                              void* d_out, int out_size)
{
    const float* x      = (const float*)d_in[0];   // [32,64,19,19]
    const float* weight = (const float*)d_in[1];   // [2,18]
    float* out          = (float*)d_out;

    const int nplanes = in_sizes[0] / NPOS;        // 2048
    const int grid = (nplanes + PLANES - 1) / PLANES;   // 512

    raycast_kernel<<<grid, THREADS>>>(x, weight, out, nplanes);
}